// round 7
// baseline (speedup 1.0000x reference)
#include <cuda_runtime.h>
#include <cuda_fp16.h>

#define CCH   32
#define R0_   128
#define R1_   512
#define HW0   (R0_ * R0_)
#define HW1   (R1_ * R1_)

// Planes laid out as [H][W/2][C=32][2] fp16: one 128B block per x-texel-pair,
// half2 per channel = (v(x_even), v(x_odd)).
__device__ __half g_xy0[HW0 * CCH];
__device__ __half g_xz0[HW0 * CCH];
__device__ __half g_yz0[HW0 * CCH];
__device__ __half g_xy1[HW1 * CCH];
__device__ __half g_xz1[HW1 * CCH];
__device__ __half g_yz1[HW1 * CCH];

#define TILES0 (HW0 / 32)
#define TILES1 (HW1 / 32)
#define TILES_ALL (3 * TILES0 + 3 * TILES1)

// Fused transpose over all 6 planes: [C, HW] fp32 -> [H][W/2][C][2] fp16.
__global__ void transpose_all_kernel(const float* __restrict__ in0,
                                     const float* __restrict__ in1,
                                     const float* __restrict__ in2,
                                     const float* __restrict__ in3,
                                     const float* __restrict__ in4,
                                     const float* __restrict__ in5,
                                     __half2* __restrict__ o0,
                                     __half2* __restrict__ o1,
                                     __half2* __restrict__ o2,
                                     __half2* __restrict__ o3,
                                     __half2* __restrict__ o4,
                                     __half2* __restrict__ o5) {
    __shared__ float tile[32][33];
    int bid = blockIdx.x;

    const float* in;
    __half2* out;
    int HW, W, pix0;
    if (bid < 3 * TILES0) {
        int plane = bid / TILES0;
        pix0 = (bid % TILES0) * 32;
        HW = HW0; W = R0_;
        in  = plane == 0 ? in0 : (plane == 1 ? in1 : in2);
        out = plane == 0 ? o0  : (plane == 1 ? o1  : o2);
    } else {
        int b = bid - 3 * TILES0;
        int plane = b / TILES1;
        pix0 = (b % TILES1) * 32;
        HW = HW1; W = R1_;
        in  = plane == 0 ? in3 : (plane == 1 ? in4 : in5);
        out = plane == 0 ? o3  : (plane == 1 ? o4  : o5);
    }

    int tx = threadIdx.x, ty = threadIdx.y;
#pragma unroll
    for (int cc = 0; cc < 32; cc += 8)
        tile[cc + ty][tx] = in[(cc + ty) * HW + pix0 + tx];
    __syncthreads();

    // 32 consecutive pixels of one row y -> 16 x-pairs.
    int y = pix0 / W;
    int xp_base = (pix0 % W) >> 1;
#pragma unroll
    for (int pp = 0; pp < 16; pp += 8) {
        int pr = pp + ty;
        __half2 v = __floats2half2_rn(tile[tx][2 * pr], tile[tx][2 * pr + 1]);
        out[((long)y * (W / 2) + xp_base + pr) * 32 + tx] = v;
    }
}

// Sample one plane for 4 channels (thread t owns channels [4t, 4t+4)).
// plane: uint4 view of [H][W/2][C][2] fp16; block = 8 uint4 = 128B.
template <int R>
__device__ __forceinline__ void sample_plane(const uint4* __restrict__ plane,
                                             float gx, float gy, int t,
                                             float acc[4]) {
    const float s = 0.5f * (float)(R - 1);
    float ix = fminf(fmaxf((gx + 1.0f) * s, 0.0f), (float)(R - 1));
    float iy = fminf(fmaxf((gy + 1.0f) * s, 0.0f), (float)(R - 1));
    int x0 = min((int)ix, R - 2);
    int y0 = min((int)iy, R - 2);
    float wx = ix - (float)x0;    // x1 = x0+1 always valid
    float wy = iy - (float)y0;

    int xp0 = x0 >> 1;
    int j0  = x0 & 1;
    long b0 = (long)y0 * (R / 2) + xp0;        // row y0 block
    long b1 = b0 + (R / 2);                    // row y0+1 block

    float v0[4], v1[4];
    uint4 A0 = __ldg(plane + b0 * 8 + t);
    uint4 A1 = __ldg(plane + b1 * 8 + t);
    if (j0 == 0) {
        const __half2* h0 = (const __half2*)&A0;
        const __half2* h1 = (const __half2*)&A1;
#pragma unroll
        for (int c = 0; c < 4; c++) {
            float2 f0 = __half22float2(h0[c]);
            float2 f1 = __half22float2(h1[c]);
            v0[c] = f0.x + wx * (f0.y - f0.x);
            v1[c] = f1.x + wx * (f1.y - f1.x);
        }
    } else {
        uint4 B0 = __ldg(plane + (b0 + 1) * 8 + t);
        uint4 B1 = __ldg(plane + (b1 + 1) * 8 + t);
        const __half2* a0 = (const __half2*)&A0;
        const __half2* a1 = (const __half2*)&A1;
        const __half2* c0 = (const __half2*)&B0;
        const __half2* c1 = (const __half2*)&B1;
#pragma unroll
        for (int c = 0; c < 4; c++) {
            float x00 = __high2float(a0[c]);   // odd texel of block A = x0
            float x01 = __low2float(c0[c]);    // even texel of block B = x1
            float x10 = __high2float(a1[c]);
            float x11 = __low2float(c1[c]);
            v0[c] = x00 + wx * (x01 - x00);
            v1[c] = x10 + wx * (x11 - x10);
        }
    }
#pragma unroll
    for (int c = 0; c < 4; c++)
        acc[c] += v0[c] + wy * (v1[c] - v0[c]);
}

// 8 threads per point; thread t owns channels [4t, 4t+4).
template <int R>
__global__ void __launch_bounds__(256)
gather3_kernel(const float* __restrict__ pts, float* __restrict__ out, int n,
               const uint4* __restrict__ pxy, const uint4* __restrict__ pxz,
               const uint4* __restrict__ pyz, int out_ofs) {
    long tid = (long)blockIdx.x * blockDim.x + threadIdx.x;
    int p = (int)(tid >> 3);
    int t = (int)(tid & 7);
    if (p >= n) return;

    float x = __ldg(pts + (long)p * 3 + 0);
    float y = __ldg(pts + (long)p * 3 + 1);
    float z = __ldg(pts + (long)p * 3 + 2);

    float acc[4] = {0.f, 0.f, 0.f, 0.f};
    sample_plane<R>(pxy, x, y, t, acc);
    sample_plane<R>(pxz, x, z, t, acc);
    sample_plane<R>(pyz, y, z, t, acc);

    // out row = 64 floats: [32 coarse | 32 fine]; this kernel writes its half.
    float4* o = (float4*)(out + (long)p * 64 + out_ofs);
    o[t] = make_float4(acc[0], acc[1], acc[2], acc[3]);
}

extern "C" void kernel_launch(void* const* d_in, const int* in_sizes, int n_in,
                              void* d_out, int out_size) {
    const float* pts = (const float*)d_in[0];
    int n = in_sizes[0] / 3;

    __half *xy0, *xz0, *yz0, *xy1, *xz1, *yz1;
    cudaGetSymbolAddress((void**)&xy0, g_xy0);
    cudaGetSymbolAddress((void**)&xz0, g_xz0);
    cudaGetSymbolAddress((void**)&yz0, g_yz0);
    cudaGetSymbolAddress((void**)&xy1, g_xy1);
    cudaGetSymbolAddress((void**)&xz1, g_xz1);
    cudaGetSymbolAddress((void**)&yz1, g_yz1);

    dim3 tb(32, 8);
    transpose_all_kernel<<<TILES_ALL, tb>>>(
        (const float*)d_in[1], (const float*)d_in[2], (const float*)d_in[3],
        (const float*)d_in[4], (const float*)d_in[5], (const float*)d_in[6],
        (__half2*)xy0, (__half2*)xz0, (__half2*)yz0,
        (__half2*)xy1, (__half2*)xz1, (__half2*)yz1);

    int threads = 256;
    long total = (long)n * 8;
    int blocks = (int)((total + threads - 1) / threads);
    gather3_kernel<R1_><<<blocks, threads>>>(pts, (float*)d_out, n,
        (const uint4*)xy1, (const uint4*)xz1, (const uint4*)yz1, 32);
    gather3_kernel<R0_><<<blocks, threads>>>(pts, (float*)d_out, n,
        (const uint4*)xy0, (const uint4*)xz0, (const uint4*)yz0, 0);
}

// round 8
// speedup vs baseline: 1.3998x; 1.3998x over previous
#include <cuda_runtime.h>
#include <cuda_fp16.h>

#define CCH   32
#define R0_   128
#define R1_   512
#define HW0   (R0_ * R0_)
#define HW1   (R1_ * R1_)

// Planes as duplicated y-pair blocks:
//   copy P (P=0,1), block k in [0, R/2), column x:
//     128B block = 32 x half2( v(row 2k+P, x), v(row 2k+P+1, x) )
// Element (half2) index: ((P*(R/2) + k)*R + x)*32 + c
__device__ __half2 g_xy0[2 * HW0 * CCH / 2];
__device__ __half2 g_xz0[2 * HW0 * CCH / 2];
__device__ __half2 g_yz0[2 * HW0 * CCH / 2];
__device__ __half2 g_xy1[2 * HW1 * CCH / 2];
__device__ __half2 g_xz1[2 * HW1 * CCH / 2];
__device__ __half2 g_yz1[2 * HW1 * CCH / 2];

// One block handles rows (2k, 2k+1, 2k+2) x 32 columns and emits both copies.
#define KB0 ((R0_ / 2) * (R0_ / 32))      // 256 blocks per coarse plane
#define KB1 ((R1_ / 2) * (R1_ / 32))      // 4096 blocks per fine plane
#define KB_ALL (3 * KB0 + 3 * KB1)        // 13056

__global__ void transpose_all_kernel(const float* __restrict__ in0,
                                     const float* __restrict__ in1,
                                     const float* __restrict__ in2,
                                     const float* __restrict__ in3,
                                     const float* __restrict__ in4,
                                     const float* __restrict__ in5,
                                     __half2* __restrict__ o0,
                                     __half2* __restrict__ o1,
                                     __half2* __restrict__ o2,
                                     __half2* __restrict__ o3,
                                     __half2* __restrict__ o4,
                                     __half2* __restrict__ o5) {
    __shared__ float t0[32][33], t1[32][33], t2[32][33];
    int bid = blockIdx.x;

    const float* in;
    __half2* out;
    int W, kidx;
    if (bid < 3 * KB0) {
        int plane = bid / KB0;
        kidx = bid % KB0;
        W = R0_;
        in  = plane == 0 ? in0 : (plane == 1 ? in1 : in2);
        out = plane == 0 ? o0  : (plane == 1 ? o1  : o2);
    } else {
        int b = bid - 3 * KB0;
        int plane = b / KB1;
        kidx = b % KB1;
        W = R1_;
        in  = plane == 0 ? in3 : (plane == 1 ? in4 : in5);
        out = plane == 0 ? o3  : (plane == 1 ? o4  : o5);
    }
    int HW = W * W;
    int k = kidx / (W / 32);
    int xbase = (kidx % (W / 32)) * 32;
    int r0 = 2 * k, r1 = 2 * k + 1, r2 = min(2 * k + 2, W - 1);

    int tx = threadIdx.x, ty = threadIdx.y;
#pragma unroll
    for (int cc = 0; cc < 32; cc += 8) {
        int c = cc + ty;
        t0[c][tx] = in[(long)c * HW + (long)r0 * W + xbase + tx];
        t1[c][tx] = in[(long)c * HW + (long)r1 * W + xbase + tx];
        t2[c][tx] = in[(long)c * HW + (long)r2 * W + xbase + tx];
    }
    __syncthreads();

    long copyB = (long)(W / 2) * W * 32;   // half2 offset of copy 1
#pragma unroll
    for (int pp = 0; pp < 32; pp += 8) {
        int x = pp + ty;
        long ia = ((long)k * W + xbase + x) * 32 + tx;
        out[ia]         = __floats2half2_rn(t0[tx][x], t1[tx][x]);
        out[copyB + ia] = __floats2half2_rn(t1[tx][x], t2[tx][x]);
    }
}

// Sample one plane for 4 channels. plane viewed as uint4; block = 8 uint4.
// Thread t (0..7) owns channels [4t, 4t+4).
template <int R>
__device__ __forceinline__ void sample_plane(const uint4* __restrict__ plane,
                                             float gx, float gy, int t,
                                             float acc[4]) {
    const float s = 0.5f * (float)(R - 1);
    float ix = fminf(fmaxf((gx + 1.0f) * s, 0.0f), (float)(R - 1));
    float iy = fminf(fmaxf((gy + 1.0f) * s, 0.0f), (float)(R - 1));
    int x0 = min((int)ix, R - 2);
    int y0 = min((int)iy, R - 2);
    float wx = ix - (float)x0;
    float wy = iy - (float)y0;

    int par = y0 & 1;
    int k   = y0 >> 1;
    long brow = ((long)par * (R / 2) + k) * R;   // block row base

    uint4 A = __ldg(plane + (brow + x0) * 8 + t);       // x0: (y0,y1) pairs
    uint4 B = __ldg(plane + (brow + x0 + 1) * 8 + t);   // x1

    const __half2* a = (const __half2*)&A;
    const __half2* b = (const __half2*)&B;
#pragma unroll
    for (int c = 0; c < 4; c++) {
        float2 f0 = __half22float2(a[c]);   // (v(y0,x0), v(y1,x0))
        float2 f1 = __half22float2(b[c]);
        float v0 = f0.x + wy * (f0.y - f0.x);
        float v1 = f1.x + wy * (f1.y - f1.x);
        acc[c] += v0 + wx * (v1 - v0);
    }
}

// 8 threads per point; thread t owns channels [4t, 4t+4) of one level.
template <int R>
__global__ void __launch_bounds__(256)
gather3_kernel(const float* __restrict__ pts, float* __restrict__ out, int n,
               const uint4* __restrict__ pxy, const uint4* __restrict__ pxz,
               const uint4* __restrict__ pyz, int out_ofs) {
    long tid = (long)blockIdx.x * blockDim.x + threadIdx.x;
    int p = (int)(tid >> 3);
    int t = (int)(tid & 7);
    if (p >= n) return;

    float x = __ldg(pts + (long)p * 3 + 0);
    float y = __ldg(pts + (long)p * 3 + 1);
    float z = __ldg(pts + (long)p * 3 + 2);

    float acc[4] = {0.f, 0.f, 0.f, 0.f};
    sample_plane<R>(pxy, x, y, t, acc);
    sample_plane<R>(pxz, x, z, t, acc);
    sample_plane<R>(pyz, y, z, t, acc);

    float4* o = (float4*)(out + (long)p * 64 + out_ofs);
    o[t] = make_float4(acc[0], acc[1], acc[2], acc[3]);
}

extern "C" void kernel_launch(void* const* d_in, const int* in_sizes, int n_in,
                              void* d_out, int out_size) {
    const float* pts = (const float*)d_in[0];
    int n = in_sizes[0] / 3;

    __half2 *xy0, *xz0, *yz0, *xy1, *xz1, *yz1;
    cudaGetSymbolAddress((void**)&xy0, g_xy0);
    cudaGetSymbolAddress((void**)&xz0, g_xz0);
    cudaGetSymbolAddress((void**)&yz0, g_yz0);
    cudaGetSymbolAddress((void**)&xy1, g_xy1);
    cudaGetSymbolAddress((void**)&xz1, g_xz1);
    cudaGetSymbolAddress((void**)&yz1, g_yz1);

    dim3 tb(32, 8);
    transpose_all_kernel<<<KB_ALL, tb>>>(
        (const float*)d_in[1], (const float*)d_in[2], (const float*)d_in[3],
        (const float*)d_in[4], (const float*)d_in[5], (const float*)d_in[6],
        xy0, xz0, yz0, xy1, xz1, yz1);

    int threads = 256;
    long total = (long)n * 8;
    int blocks = (int)((total + threads - 1) / threads);
    gather3_kernel<R1_><<<blocks, threads>>>(pts, (float*)d_out, n,
        (const uint4*)xy1, (const uint4*)xz1, (const uint4*)yz1, 32);
    gather3_kernel<R0_><<<blocks, threads>>>(pts, (float*)d_out, n,
        (const uint4*)xy0, (const uint4*)xz0, (const uint4*)yz0, 0);
}